// round 16
// baseline (speedup 1.0000x reference)
#include <cuda_runtime.h>
#include <cuda_fp16.h>
#include <math.h>
#include <stdint.h>

#define N_NODES 50000
#define N_EDGES 1600000
#define F_IN 128
#define C 64
#define NG 512
#define CATC 192
#define MLP_DIM 128
#define N_CLASSES 10
#define MAX_PE 3200000
#define MAX_GROUPS 163840
#define EDGE_GRID 444
#define NWARPS (EDGE_GRID * 8)
#define ENC_NINF 0x007FFFFFu
#define SCAN_BLKS 196
#define DEC_GRID 256
#define AB_GRID 98                /* 4 tiles per block: 98*32 = 3136 >= 3125 */

// ---------------- scratch ----------------
__device__ float    d_h[N_NODES * C];
__device__ __half   d_Ah[N_NODES * C];
__device__ __half   d_Bh[N_NODES * C];
__device__ unsigned d_agg[N_NODES * C];
__device__ float    d_cat[N_NODES * CATC];
__device__ int      d_cnt[N_NODES];
__device__ int      d_cur[N_NODES];
__device__ int      d_srcP[MAX_PE];
__device__ int      d_gdst[MAX_GROUPS];
__device__ int      d_gcnt[MAX_GROUPS];
__device__ int      d_ngroups;
__device__ int      d_bsumE[SCAN_BLKS];
__device__ int      d_bsumG[SCAN_BLKS];
__device__ int      d_boffE[SCAN_BLKS];
__device__ int      d_boffG[SCAN_BLKS];
__device__ double   d_bn[2 * C];
__device__ float    d_scale[C];
__device__ float    d_shift[C];
__device__ float    d_pooled[NG * CATC];
__device__ int      d_start[NG + 1];
__device__ int      d_ei32 = 0;
__device__ int      d_b32 = 0;

__device__ __forceinline__ unsigned encf(float f) {
    unsigned u = __float_as_uint(f);
    unsigned mask = (unsigned)((int)u >> 31) | 0x80000000u;
    return u ^ mask;
}
__device__ __forceinline__ float decf(unsigned v) {
    unsigned mask = (v & 0x80000000u) ? 0x80000000u : 0xFFFFFFFFu;
    return __uint_as_float(v ^ mask);
}
__device__ __forceinline__ int load_idx(const void* p, long long i, int is32) {
    if (is32) return ((const int*)p)[i];
    return (int)((const long long*)p)[i];
}
__device__ __forceinline__ uint32_t pack_h2(float x, float y) {
    __half2 p = __floats2half2_rn(x, y);
    return *(uint32_t*)&p;
}
__device__ __forceinline__ uint32_t haz(uint32_t a, uint32_t b) {
    __half2 s = __hadd2(*(__half2*)&a, *(__half2*)&b);
    __half2 z = __float2half2_rn(0.f);
    __half2 m = __hmax2(s, z);
    return *(uint32_t*)&m;
}
__device__ __forceinline__ void mma_f16(float& d0, float& d1, float& d2, float& d3,
                                        uint32_t a0, uint32_t a1, uint32_t a2, uint32_t a3,
                                        uint32_t b0, uint32_t b1) {
    asm volatile(
        "mma.sync.aligned.m16n8k16.row.col.f32.f16.f16.f32 "
        "{%0,%1,%2,%3}, {%4,%5,%6,%7}, {%8,%9}, {%0,%1,%2,%3};"
        : "+f"(d0), "+f"(d1), "+f"(d2), "+f"(d3)
        : "r"(a0), "r"(a1), "r"(a2), "r"(a3), "r"(b0), "r"(b1));
}

// ---------------- dtype detection ----------------
__global__ void detect_kernel(const int* __restrict__ ei, const int* __restrict__ batch) {
    int t = blockIdx.x * 256 + threadIdx.x;
    long long p1 = (((long long)t * 700001LL) % (2LL * N_EDGES)) | 1LL;
    if (ei[p1] != 0) d_ei32 = 1;
    long long p2 = (((long long)t * 12197LL) % (long long)N_NODES) | 1LL;
    if (batch[p2] != 0) d_b32 = 1;
}

// ---------------- fc0 via tensor cores (4 tiles/block) ----------------
__global__ void __launch_bounds__(256) fc0_kernel(const float* __restrict__ x,
                                                  const float* __restrict__ w,
                                                  const float* __restrict__ b) {
    __shared__ uint2 s_wf[2048];
    __shared__ float s_b[64];
    int t = threadIdx.x, wv = t >> 5, l = t & 31;
    int r = l >> 2, c4 = l & 3;

    for (int idx = t; idx < 2048; idx += 256) {
        int lane = idx & 31, fi = idx >> 5;   // fi = nt*8 + kt
        int nt = fi >> 3, kt = fi & 7;
        int n = nt * 8 + (lane >> 2), c = lane & 3;
        int k0 = kt * 16 + 2 * c;
        s_wf[idx] = make_uint2(pack_h2(w[k0 * 64 + n], w[(k0 + 1) * 64 + n]),
                               pack_h2(w[(k0 + 8) * 64 + n], w[(k0 + 9) * 64 + n]));
    }
    if (t < 64) s_b[t] = b[t];
    __syncthreads();

    for (int it = 0; it < 4; it++) {
        int n0 = (blockIdx.x * 32 + it * 8 + wv) * 16;
        if (n0 >= N_NODES) continue;

        const float* xr0 = &x[(n0 + r) * 128];
        const float* xr1 = &x[(n0 + r + 8) * 128];
        uint32_t af[8][4];
#pragma unroll
        for (int kt = 0; kt < 8; kt++) {
            int k0 = kt * 16 + 2 * c4;
            float2 a0 = *(const float2*)&xr0[k0];
            float2 a1 = *(const float2*)&xr1[k0];
            float2 a2 = *(const float2*)&xr0[k0 + 8];
            float2 a3 = *(const float2*)&xr1[k0 + 8];
            af[kt][0] = pack_h2(a0.x, a0.y);
            af[kt][1] = pack_h2(a1.x, a1.y);
            af[kt][2] = pack_h2(a2.x, a2.y);
            af[kt][3] = pack_h2(a3.x, a3.y);
        }

#pragma unroll
        for (int nt = 0; nt < 8; nt++) {
            float d0 = 0.f, d1 = 0.f, d2 = 0.f, d3 = 0.f;
#pragma unroll
            for (int kt = 0; kt < 8; kt++) {
                uint2 f = s_wf[(nt * 8 + kt) * 32 + l];
                mma_f16(d0, d1, d2, d3, af[kt][0], af[kt][1], af[kt][2], af[kt][3], f.x, f.y);
            }
            int out0 = nt * 8 + 2 * c4;
            float2 bb = *(const float2*)&s_b[out0];
            *(float2*)&d_h[(n0 + r) * 64 + out0]     = make_float2(d0 + bb.x, d1 + bb.y);
            *(float2*)&d_h[(n0 + r + 8) * 64 + out0] = make_float2(d2 + bb.x, d3 + bb.y);
        }
    }
}

// ---------------- batchnorm stats ----------------
#define BN_GRID 256
__global__ void __launch_bounds__(256) bn_stats() {
    __shared__ float sh[2][16][64];
    int t = threadIdx.x;
    int cq = t & 15, g = t >> 4;
    float s0 = 0.f, s1 = 0.f, s2 = 0.f, s3 = 0.f;
    float q0 = 0.f, q1 = 0.f, q2 = 0.f, q3 = 0.f;
    for (int n = blockIdx.x * 16 + g; n < N_NODES; n += BN_GRID * 16) {
        float4 v = *(const float4*)&d_h[n * 64 + cq * 4];
        s0 += v.x; s1 += v.y; s2 += v.z; s3 += v.w;
        q0 += v.x * v.x; q1 += v.y * v.y; q2 += v.z * v.z; q3 += v.w * v.w;
    }
    sh[0][g][cq * 4 + 0] = s0; sh[0][g][cq * 4 + 1] = s1;
    sh[0][g][cq * 4 + 2] = s2; sh[0][g][cq * 4 + 3] = s3;
    sh[1][g][cq * 4 + 0] = q0; sh[1][g][cq * 4 + 1] = q1;
    sh[1][g][cq * 4 + 2] = q2; sh[1][g][cq * 4 + 3] = q3;
    __syncthreads();
    if (t < 64) {
        float S = 0.f, Q = 0.f;
#pragma unroll
        for (int j = 0; j < 16; j++) { S += sh[0][j][t]; Q += sh[1][j][t]; }
        atomicAdd(&d_bn[t], (double)S);
        atomicAdd(&d_bn[64 + t], (double)Q);
    }
}
__global__ void bn_final(const float* __restrict__ gg, const float* __restrict__ bb) {
    int c = threadIdx.x;
    double mean = d_bn[c] / (double)N_NODES;
    double var = d_bn[64 + c] / (double)N_NODES - mean * mean;
    double sc = (double)gg[c] / sqrt(var + 1e-5);
    d_scale[c] = (float)sc;
    d_shift[c] = (float)((double)bb[c] - mean * sc);
    d_bn[c] = 0.0;
    d_bn[64 + c] = 0.0;
}

// ---------------- A/B precompute via tensor cores (4 tiles/block) ----------------
__global__ void __launch_bounds__(256) ab_kernel(const float* __restrict__ w1,
                                                 const float* __restrict__ b1) {
    __shared__ uint2 s_wf[2048];
    __shared__ float s_b1[64];
    int t = threadIdx.x, w = t >> 5, l = t & 31;
    int r = l >> 2, c4 = l & 3;

    for (int idx = t; idx < 2048; idx += 256) {
        int lane = idx & 31, fi = idx >> 5;
        int nt = fi >> 2, kt = fi & 3;
        int n = nt * 8 + (lane >> 2), c = lane & 3;
        int k0 = kt * 16 + 2 * c;
        float v00, v01, v10, v11;
        if (n < 64) {
            v00 = w1[k0 * 64 + n]       - w1[(k0 + 64) * 64 + n];
            v01 = w1[(k0 + 1) * 64 + n] - w1[(k0 + 65) * 64 + n];
            v10 = w1[(k0 + 8) * 64 + n] - w1[(k0 + 72) * 64 + n];
            v11 = w1[(k0 + 9) * 64 + n] - w1[(k0 + 73) * 64 + n];
        } else {
            int m = n - 64;
            v00 = w1[(k0 + 64) * 64 + m];
            v01 = w1[(k0 + 65) * 64 + m];
            v10 = w1[(k0 + 72) * 64 + m];
            v11 = w1[(k0 + 73) * 64 + m];
        }
        s_wf[idx] = make_uint2(pack_h2(v00, v01), pack_h2(v10, v11));
    }
    if (t < 64) s_b1[t] = b1[t];
    __syncthreads();

    float sc[4][4], sf[4][4];
#pragma unroll
    for (int kt = 0; kt < 4; kt++) {
        int k0 = kt * 16 + 2 * c4;
        sc[kt][0] = d_scale[k0];     sf[kt][0] = d_shift[k0];
        sc[kt][1] = d_scale[k0 + 1]; sf[kt][1] = d_shift[k0 + 1];
        sc[kt][2] = d_scale[k0 + 8]; sf[kt][2] = d_shift[k0 + 8];
        sc[kt][3] = d_scale[k0 + 9]; sf[kt][3] = d_shift[k0 + 9];
    }

    for (int it = 0; it < 4; it++) {
        int n0 = (blockIdx.x * 32 + it * 8 + w) * 16;
        if (n0 >= N_NODES) continue;

        uint32_t af[4][4];
#pragma unroll
        for (int kt = 0; kt < 4; kt++) {
            int k0 = kt * 16 + 2 * c4;
            float2 h0a = *(const float2*)&d_h[(n0 + r) * 64 + k0];
            float2 h0b = *(const float2*)&d_h[(n0 + r) * 64 + k0 + 8];
            float2 h1a = *(const float2*)&d_h[(n0 + r + 8) * 64 + k0];
            float2 h1b = *(const float2*)&d_h[(n0 + r + 8) * 64 + k0 + 8];
            af[kt][0] = pack_h2(h0a.x * sc[kt][0] + sf[kt][0], h0a.y * sc[kt][1] + sf[kt][1]);
            af[kt][1] = pack_h2(h1a.x * sc[kt][0] + sf[kt][0], h1a.y * sc[kt][1] + sf[kt][1]);
            af[kt][2] = pack_h2(h0b.x * sc[kt][2] + sf[kt][2], h0b.y * sc[kt][3] + sf[kt][3]);
            af[kt][3] = pack_h2(h1b.x * sc[kt][2] + sf[kt][2], h1b.y * sc[kt][3] + sf[kt][3]);
        }

#pragma unroll
        for (int nt = 0; nt < 16; nt++) {
            float d0 = 0.f, d1 = 0.f, d2 = 0.f, d3 = 0.f;
#pragma unroll
            for (int kt = 0; kt < 4; kt++) {
                uint2 f = s_wf[(nt * 4 + kt) * 32 + l];
                mma_f16(d0, d1, d2, d3, af[kt][0], af[kt][1], af[kt][2], af[kt][3], f.x, f.y);
            }
            int out0 = nt * 8 + 2 * c4;
            if (nt < 8) {
                float bb0 = s_b1[out0], bb1 = s_b1[out0 + 1];
                d0 += bb0; d1 += bb1; d2 += bb0; d3 += bb1;
            }
            int off = c4 * 16 + ((nt & 7) >> 1) * 4 + (nt & 1) * 2;
            __half2 lo = __floats2half2_rn(d0, d1);
            __half2 hi = __floats2half2_rn(d2, d3);
            if (nt < 8) {
                *(__half2*)&d_Ah[(n0 + r) * 64 + off]     = lo;
                *(__half2*)&d_Ah[(n0 + r + 8) * 64 + off] = hi;
            } else {
                *(__half2*)&d_Bh[(n0 + r) * 64 + off]     = lo;
                *(__half2*)&d_Bh[(n0 + r + 8) * 64 + off] = hi;
            }
        }
    }
}

// ---------------- counting sort (16-padded groups) ----------------
__global__ void hist_kernel(const void* __restrict__ ei) {
    int e = blockIdx.x * 256 + threadIdx.x;
    int dd = load_idx(ei, (long long)N_EDGES + e, d_ei32);
    atomicAdd(&d_cnt[dd], 1);
}
__global__ void __launch_bounds__(256) scan_part() {
    __shared__ int sE[256], sG[256];
    int t = threadIdx.x;
    int node = blockIdx.x * 256 + t;
    int c = (node < N_NODES) ? d_cnt[node] : 0;
    int ngn = (c + 15) >> 4;
    sE[t] = ngn * 16; sG[t] = ngn;
    __syncthreads();
    for (int off = 128; off > 0; off >>= 1) {
        if (t < off) { sE[t] += sE[t + off]; sG[t] += sG[t + off]; }
        __syncthreads();
    }
    if (t == 0) { d_bsumE[blockIdx.x] = sE[0]; d_bsumG[blockIdx.x] = sG[0]; }
}
__global__ void __launch_bounds__(256) scan_mid() {
    __shared__ int sE[256], sG[256];
    int t = threadIdx.x;
    sE[t] = (t < SCAN_BLKS) ? d_bsumE[t] : 0;
    sG[t] = (t < SCAN_BLKS) ? d_bsumG[t] : 0;
    __syncthreads();
    for (int off = 1; off < 256; off <<= 1) {
        int vE = (t >= off) ? sE[t - off] : 0;
        int vG = (t >= off) ? sG[t - off] : 0;
        __syncthreads();
        sE[t] += vE; sG[t] += vG;
        __syncthreads();
    }
    if (t < SCAN_BLKS) {
        d_boffE[t] = sE[t] - d_bsumE[t];
        d_boffG[t] = sG[t] - d_bsumG[t];
    }
    if (t == SCAN_BLKS - 1) d_ngroups = sG[t];
}
__global__ void __launch_bounds__(256) scan_emit() {
    __shared__ int sE[256], sG[256];
    int t = threadIdx.x;
    int node = blockIdx.x * 256 + t;
    int c = (node < N_NODES) ? d_cnt[node] : 0;
    int ngn = (c + 15) >> 4;
    sE[t] = ngn * 16; sG[t] = ngn;
    __syncthreads();
    for (int off = 1; off < 256; off <<= 1) {
        int vE = (t >= off) ? sE[t - off] : 0;
        int vG = (t >= off) ? sG[t - off] : 0;
        __syncthreads();
        sE[t] += vE; sG[t] += vG;
        __syncthreads();
    }
    if (node < N_NODES) {
        int ebase = d_boffE[blockIdx.x] + sE[t] - ngn * 16;
        int gbase = d_boffG[blockIdx.x] + sG[t] - ngn;
        d_cur[node] = ebase;
        for (int j = 0; j < ngn; j++) {
            d_gdst[gbase + j] = node;
            int rem = c - 16 * j;
            d_gcnt[gbase + j] = rem < 16 ? rem : 16;
        }
        d_cnt[node] = 0;
    }
}
__global__ void scatter_kernel(const void* __restrict__ ei) {
    int e = blockIdx.x * 256 + threadIdx.x;
    int is32 = d_ei32;
    int ss = load_idx(ei, e, is32);
    int dd = load_idx(ei, (long long)N_EDGES + e, is32);
    int p = atomicAdd(&d_cur[dd], 1);
    d_srcP[p] = ss;
}

__global__ void agg_init() { d_agg[blockIdx.x * 256 + threadIdx.x] = ENC_NINF; }

// ---------------- edge kernel: chunked contiguous group assignment ----------------
__global__ void __launch_bounds__(256, 3) edge_kernel(const float* __restrict__ w2) {
    __shared__ uint4 s_wf[16 * 32];
    int t = threadIdx.x, w = t >> 5, l = t & 31;

    for (int idx = t; idx < 512; idx += 256) {
        int lane = idx & 31, fi = idx >> 5;
        int chb = fi >> 2, kt = fi & 3;
        int rr = lane >> 2, cc = lane & 3;
        int ch0 = chb * 16 + rr, ch1 = ch0 + 8;
        int k0 = kt * 16 + 2 * cc;
        uint32_t a0 = pack_h2(w2[k0 * 64 + ch0],       w2[(k0 + 1) * 64 + ch0]);
        uint32_t a1 = pack_h2(w2[k0 * 64 + ch1],       w2[(k0 + 1) * 64 + ch1]);
        uint32_t a2 = pack_h2(w2[(k0 + 8) * 64 + ch0], w2[(k0 + 9) * 64 + ch0]);
        uint32_t a3 = pack_h2(w2[(k0 + 8) * 64 + ch1], w2[(k0 + 9) * 64 + ch1]);
        s_wf[idx] = make_uint4(a0, a1, a2, a3);
    }
    __syncthreads();

    int ng = d_ngroups;
    int r = l >> 2, c4 = l & 3;
    const uint4* pA = (const uint4*)d_Ah;
    const uint4* pB = (const uint4*)d_Bh;
    const float NINF = -__int_as_float(0x7F800000) * 1.f;

    // contiguous chunk of groups per warp (locality in gdst/srcP/A-rows)
    int per = (ng + NWARPS - 1) / NWARPS;
    int g0 = (blockIdx.x * 8 + w) * per;
    int gend = g0 + per;
    if (gend > ng) gend = ng;

    for (int g = g0; g < gend; g++) {
        int gd = d_gdst[g];
        int gc = d_gcnt[g];
        uint4 Au0 = pA[gd * 8 + c4 * 2];
        uint4 Au1 = pA[gd * 8 + c4 * 2 + 1];

        float vmax[4][2];
#pragma unroll
        for (int i = 0; i < 4; i++) { vmax[i][0] = NINF; vmax[i][1] = NINF; }

#pragma unroll
        for (int eb = 0; eb < 2; eb++) {
            int ns = d_srcP[g * 16 + eb * 8 + r];
            uint4 Bu0 = pB[ns * 8 + c4 * 2];
            uint4 Bu1 = pB[ns * 8 + c4 * 2 + 1];
            uint32_t p00 = haz(Au0.x, Bu0.x), p01 = haz(Au0.y, Bu0.y);
            uint32_t p10 = haz(Au0.z, Bu0.z), p11 = haz(Au0.w, Bu0.w);
            uint32_t p20 = haz(Au1.x, Bu1.x), p21 = haz(Au1.y, Bu1.y);
            uint32_t p30 = haz(Au1.z, Bu1.z), p31 = haz(Au1.w, Bu1.w);
            int e0 = eb * 8 + 2 * c4;
            bool m0 = e0 < gc, m1 = e0 + 1 < gc;
#pragma unroll
            for (int chb = 0; chb < 4; chb++) {
                float d0 = 0.f, d1 = 0.f, d2 = 0.f, d3 = 0.f;
                uint4 f;
                f = s_wf[(chb * 4 + 0) * 32 + l];
                mma_f16(d0, d1, d2, d3, f.x, f.y, f.z, f.w, p00, p01);
                f = s_wf[(chb * 4 + 1) * 32 + l];
                mma_f16(d0, d1, d2, d3, f.x, f.y, f.z, f.w, p10, p11);
                f = s_wf[(chb * 4 + 2) * 32 + l];
                mma_f16(d0, d1, d2, d3, f.x, f.y, f.z, f.w, p20, p21);
                f = s_wf[(chb * 4 + 3) * 32 + l];
                mma_f16(d0, d1, d2, d3, f.x, f.y, f.z, f.w, p30, p31);
                vmax[chb][0] = fmaxf(vmax[chb][0], m0 ? d0 : NINF);
                vmax[chb][0] = fmaxf(vmax[chb][0], m1 ? d1 : NINF);
                vmax[chb][1] = fmaxf(vmax[chb][1], m0 ? d2 : NINF);
                vmax[chb][1] = fmaxf(vmax[chb][1], m1 ? d3 : NINF);
            }
        }

#pragma unroll
        for (int chb = 0; chb < 4; chb++) {
#pragma unroll
            for (int j = 0; j < 2; j++) {
                float v = vmax[chb][j];
                v = fmaxf(v, __shfl_xor_sync(0xFFFFFFFFu, v, 1));
                v = fmaxf(v, __shfl_xor_sync(0xFFFFFFFFu, v, 2));
                vmax[chb][j] = v;
            }
        }
        if (c4 == 0) {
#pragma unroll
            for (int chb = 0; chb < 4; chb++) {
#pragma unroll
                for (int j = 0; j < 2; j++) {
                    int ch = chb * 16 + j * 8 + r;
                    atomicMax(&d_agg[gd * 64 + ch], encf(vmax[chb][j]));
                }
            }
        }
    }
}

// ---------------- decode fused with bn partials ----------------
__global__ void __launch_bounds__(256) decode_bn_kernel(int blk,
                                                        const float* __restrict__ b2,
                                                        int do_bn) {
    __shared__ float sh[2][16][64];
    int t = threadIdx.x;
    int cq = t & 15, g = t >> 4;
    float4 bb = *(const float4*)&b2[cq * 4];
    float s0 = 0.f, s1 = 0.f, s2 = 0.f, s3 = 0.f;
    float q0 = 0.f, q1 = 0.f, q2 = 0.f, q3 = 0.f;
    for (int n = blockIdx.x * 16 + g; n < N_NODES; n += DEC_GRID * 16) {
        uint4 e = *(uint4*)&d_agg[n * 64 + cq * 4];
        *(uint4*)&d_agg[n * 64 + cq * 4] = make_uint4(ENC_NINF, ENC_NINF, ENC_NINF, ENC_NINF);
        float v0 = (e.x == ENC_NINF) ? 0.f : fmaxf(decf(e.x) + bb.x, 0.f);
        float v1 = (e.y == ENC_NINF) ? 0.f : fmaxf(decf(e.y) + bb.y, 0.f);
        float v2 = (e.z == ENC_NINF) ? 0.f : fmaxf(decf(e.z) + bb.z, 0.f);
        float v3 = (e.w == ENC_NINF) ? 0.f : fmaxf(decf(e.w) + bb.w, 0.f);
        float4 vv = make_float4(v0, v1, v2, v3);
        *(float4*)&d_h[n * 64 + cq * 4] = vv;
        *(float4*)&d_cat[n * CATC + blk * 64 + cq * 4] = vv;
        s0 += v0; s1 += v1; s2 += v2; s3 += v3;
        q0 += v0 * v0; q1 += v1 * v1; q2 += v2 * v2; q3 += v3 * v3;
    }
    if (!do_bn) return;
    sh[0][g][cq * 4 + 0] = s0; sh[0][g][cq * 4 + 1] = s1;
    sh[0][g][cq * 4 + 2] = s2; sh[0][g][cq * 4 + 3] = s3;
    sh[1][g][cq * 4 + 0] = q0; sh[1][g][cq * 4 + 1] = q1;
    sh[1][g][cq * 4 + 2] = q2; sh[1][g][cq * 4 + 3] = q3;
    __syncthreads();
    if (t < 64) {
        float S = 0.f, Q = 0.f;
#pragma unroll
        for (int j = 0; j < 16; j++) { S += sh[0][j][t]; Q += sh[1][j][t]; }
        atomicAdd(&d_bn[t], (double)S);
        atomicAdd(&d_bn[64 + t], (double)Q);
    }
}

// ---------------- pooling ----------------
__global__ void pool_start(const void* __restrict__ batch) {
    int g = blockIdx.x * 256 + threadIdx.x;
    if (g > NG) return;
    int is32 = d_b32;
    int lo = 0, hi = N_NODES;
    while (lo < hi) {
        int mid = (lo + hi) >> 1;
        if (load_idx(batch, mid, is32) < g) lo = mid + 1; else hi = mid;
    }
    d_start[g] = lo;
}
__global__ void pool_kernel() {
    int g = blockIdx.x, t = threadIdx.x;
    int s = d_start[g], e = d_start[g + 1];
    float acc = 0.f;
    for (int n = s; n < e; n++) acc += d_cat[n * CATC + t];
    int cnt = e - s; if (cnt < 1) cnt = 1;
    d_pooled[g * CATC + t] = acc / (float)cnt;
}

// ---------------- head ----------------
__global__ void head_kernel(const float* __restrict__ w1, const float* __restrict__ b1,
                            const float* __restrict__ w2, const float* __restrict__ b2,
                            float* __restrict__ out) {
    __shared__ float sp[CATC];
    __shared__ float shid[MLP_DIM];
    __shared__ float sl[N_CLASSES];
    __shared__ float s_ls;
    int g = blockIdx.x, t = threadIdx.x;
    sp[t] = d_pooled[g * CATC + t];
    __syncthreads();
    if (t < MLP_DIM) {
        float a = b1[t];
#pragma unroll 8
        for (int k = 0; k < CATC; k++) a += sp[k] * w1[k * MLP_DIM + t];
        shid[t] = fmaxf(a, 0.f);
    }
    __syncthreads();
    if (t < N_CLASSES) {
        float a = b2[t];
#pragma unroll 8
        for (int k = 0; k < MLP_DIM; k++) a += shid[k] * w2[k * N_CLASSES + t];
        sl[t] = a;
    }
    __syncthreads();
    if (t == 0) {
        float mx = sl[0];
        for (int i = 1; i < N_CLASSES; i++) mx = fmaxf(mx, sl[i]);
        float se = 0.f;
        for (int i = 0; i < N_CLASSES; i++) se += expf(sl[i] - mx);
        s_ls = mx + logf(se);
    }
    __syncthreads();
    if (t < N_CLASSES) out[g * N_CLASSES + t] = sl[t] - s_ls;
}

// ---------------- launch ----------------
extern "C" void kernel_launch(void* const* d_in, const int* in_sizes, int n_in,
                              void* d_out, int out_size) {
    const float* x     = (const float*)d_in[0];
    const void*  ei    = d_in[1];
    const void*  batch = d_in[2];
    const float* fc0_w = (const float*)d_in[3];
    const float* fc0_b = (const float*)d_in[4];
    const float* fc1_w = (const float*)d_in[5];
    const float* fc1_b = (const float*)d_in[6];
    const float* fc2_w = (const float*)d_in[7];
    const float* fc2_b = (const float*)d_in[8];
    const float* bnp[3][6];
    for (int i = 0; i < 3; i++)
        for (int j = 0; j < 6; j++)
            bnp[i][j] = (const float*)d_in[9 + 6 * i + j];
    float* out = (float*)d_out;

    fc0_kernel<<<AB_GRID, 256>>>(x, fc0_w, fc0_b);                   // 1
    bn_stats<<<BN_GRID, 256>>>();                                    // 2
    bn_final<<<1, 64>>>(bnp[0][0], bnp[0][1]);                       // 3
    ab_kernel<<<AB_GRID, 256>>>(bnp[0][2], bnp[0][3]);               // 4 (profiled)
    detect_kernel<<<16, 256>>>((const int*)ei, (const int*)batch);   // 5
    hist_kernel<<<N_EDGES / 256, 256>>>(ei);                         // 6
    scan_part<<<SCAN_BLKS, 256>>>();                                 // 7
    scan_mid<<<1, 256>>>();                                          // 8
    scan_emit<<<SCAN_BLKS, 256>>>();                                 // 9
    scatter_kernel<<<N_EDGES / 256, 256>>>(ei);                      // 10
    agg_init<<<(N_NODES * C) / 256, 256>>>();                        // 11

    for (int i = 0; i < 3; i++) {
        if (i > 0) {
            bn_final<<<1, 64>>>(bnp[i][0], bnp[i][1]);
            ab_kernel<<<AB_GRID, 256>>>(bnp[i][2], bnp[i][3]);
        }
        edge_kernel<<<EDGE_GRID, 256>>>(bnp[i][4]);
        decode_bn_kernel<<<DEC_GRID, 256>>>(i, bnp[i][5], i < 2 ? 1 : 0);
    }

    pool_start<<<3, 256>>>(batch);
    pool_kernel<<<NG, CATC>>>();
    head_kernel<<<NG, CATC>>>(fc1_w, fc1_b, fc2_w, fc2_b, out);
}

// round 17
// speedup vs baseline: 1.0648x; 1.0648x over previous
#include <cuda_runtime.h>
#include <cuda_fp16.h>
#include <math.h>
#include <stdint.h>

#define N_NODES 50000
#define N_EDGES 1600000
#define F_IN 128
#define C 64
#define NG 512
#define CATC 192
#define MLP_DIM 128
#define N_CLASSES 10
#define MAX_PE 3200000
#define MAX_GROUPS 163840
#define EDGE_GRID 444
#define NWARPS (EDGE_GRID * 8)
#define ENC_NINF 0x007FFFFFu
#define SCAN_BLKS 196
#define DEC_GRID 256
#define AB_GRID 391

// ---------------- scratch ----------------
__device__ float    d_h[N_NODES * C];
__device__ __half   d_Ah[N_NODES * C];
__device__ __half   d_Bh[N_NODES * C];
__device__ unsigned d_agg[N_NODES * C];
__device__ float    d_cat[N_NODES * CATC];
__device__ int      d_cnt[N_NODES];
__device__ int      d_cur[N_NODES];
__device__ int      d_srcP[MAX_PE];
__device__ int      d_gdst[MAX_GROUPS];
__device__ int      d_gcnt[MAX_GROUPS];
__device__ int      d_ngroups;
__device__ int      d_bsumE[SCAN_BLKS];
__device__ int      d_bsumG[SCAN_BLKS];
__device__ int      d_boffE[SCAN_BLKS];
__device__ int      d_boffG[SCAN_BLKS];
__device__ double   d_bn[2 * C];
__device__ float    d_scale[C];
__device__ float    d_shift[C];
__device__ int      d_ei32 = 0;
__device__ int      d_b32 = 0;

__device__ __forceinline__ unsigned encf(float f) {
    unsigned u = __float_as_uint(f);
    unsigned mask = (unsigned)((int)u >> 31) | 0x80000000u;
    return u ^ mask;
}
__device__ __forceinline__ float decf(unsigned v) {
    unsigned mask = (v & 0x80000000u) ? 0x80000000u : 0xFFFFFFFFu;
    return __uint_as_float(v ^ mask);
}
__device__ __forceinline__ int load_idx(const void* p, long long i, int is32) {
    if (is32) return ((const int*)p)[i];
    return (int)((const long long*)p)[i];
}
__device__ __forceinline__ uint32_t pack_h2(float x, float y) {
    __half2 p = __floats2half2_rn(x, y);
    return *(uint32_t*)&p;
}
__device__ __forceinline__ uint32_t haz(uint32_t a, uint32_t b) {
    __half2 s = __hadd2(*(__half2*)&a, *(__half2*)&b);
    __half2 z = __float2half2_rn(0.f);
    __half2 m = __hmax2(s, z);
    return *(uint32_t*)&m;
}
__device__ __forceinline__ void mma_f16(float& d0, float& d1, float& d2, float& d3,
                                        uint32_t a0, uint32_t a1, uint32_t a2, uint32_t a3,
                                        uint32_t b0, uint32_t b1) {
    asm volatile(
        "mma.sync.aligned.m16n8k16.row.col.f32.f16.f16.f32 "
        "{%0,%1,%2,%3}, {%4,%5,%6,%7}, {%8,%9}, {%0,%1,%2,%3};"
        : "+f"(d0), "+f"(d1), "+f"(d2), "+f"(d3)
        : "r"(a0), "r"(a1), "r"(a2), "r"(a3), "r"(b0), "r"(b1));
}

// ---------------- dtype detection ----------------
__global__ void detect_kernel(const int* __restrict__ ei, const int* __restrict__ batch) {
    int t = blockIdx.x * 256 + threadIdx.x;
    long long p1 = (((long long)t * 700001LL) % (2LL * N_EDGES)) | 1LL;
    if (ei[p1] != 0) d_ei32 = 1;
    long long p2 = (((long long)t * 12197LL) % (long long)N_NODES) | 1LL;
    if (batch[p2] != 0) d_b32 = 1;
}

// ---------------- fc0 via tensor cores (single tile/block; 434.7us config) ----------------
__global__ void __launch_bounds__(256) fc0_kernel(const float* __restrict__ x,
                                                  const float* __restrict__ w,
                                                  const float* __restrict__ b) {
    __shared__ uint2 s_wf[2048];
    __shared__ float s_b[64];
    int t = threadIdx.x, wv = t >> 5, l = t & 31;
    int r = l >> 2, c4 = l & 3;

    for (int idx = t; idx < 2048; idx += 256) {
        int lane = idx & 31, fi = idx >> 5;   // fi = nt*8 + kt
        int nt = fi >> 3, kt = fi & 7;
        int n = nt * 8 + (lane >> 2), c = lane & 3;
        int k0 = kt * 16 + 2 * c;
        s_wf[idx] = make_uint2(pack_h2(w[k0 * 64 + n], w[(k0 + 1) * 64 + n]),
                               pack_h2(w[(k0 + 8) * 64 + n], w[(k0 + 9) * 64 + n]));
    }
    if (t < 64) s_b[t] = b[t];
    __syncthreads();

    int n0 = (blockIdx.x * 8 + wv) * 16;
    if (n0 >= N_NODES) return;

    const float* xr0 = &x[(n0 + r) * 128];
    const float* xr1 = &x[(n0 + r + 8) * 128];
    uint32_t af[8][4];
#pragma unroll
    for (int kt = 0; kt < 8; kt++) {
        int k0 = kt * 16 + 2 * c4;
        float2 a0 = *(const float2*)&xr0[k0];
        float2 a1 = *(const float2*)&xr1[k0];
        float2 a2 = *(const float2*)&xr0[k0 + 8];
        float2 a3 = *(const float2*)&xr1[k0 + 8];
        af[kt][0] = pack_h2(a0.x, a0.y);
        af[kt][1] = pack_h2(a1.x, a1.y);
        af[kt][2] = pack_h2(a2.x, a2.y);
        af[kt][3] = pack_h2(a3.x, a3.y);
    }

#pragma unroll
    for (int nt = 0; nt < 8; nt++) {
        float d0 = 0.f, d1 = 0.f, d2 = 0.f, d3 = 0.f;
#pragma unroll
        for (int kt = 0; kt < 8; kt++) {
            uint2 f = s_wf[(nt * 8 + kt) * 32 + l];
            mma_f16(d0, d1, d2, d3, af[kt][0], af[kt][1], af[kt][2], af[kt][3], f.x, f.y);
        }
        int out0 = nt * 8 + 2 * c4;
        float2 bb = *(const float2*)&s_b[out0];
        *(float2*)&d_h[(n0 + r) * 64 + out0]     = make_float2(d0 + bb.x, d1 + bb.y);
        *(float2*)&d_h[(n0 + r + 8) * 64 + out0] = make_float2(d2 + bb.x, d3 + bb.y);
    }
}

// ---------------- batchnorm stats ----------------
#define BN_GRID 256
__global__ void __launch_bounds__(256) bn_stats() {
    __shared__ float sh[2][16][64];
    int t = threadIdx.x;
    int cq = t & 15, g = t >> 4;
    float s0 = 0.f, s1 = 0.f, s2 = 0.f, s3 = 0.f;
    float q0 = 0.f, q1 = 0.f, q2 = 0.f, q3 = 0.f;
    for (int n = blockIdx.x * 16 + g; n < N_NODES; n += BN_GRID * 16) {
        float4 v = *(const float4*)&d_h[n * 64 + cq * 4];
        s0 += v.x; s1 += v.y; s2 += v.z; s3 += v.w;
        q0 += v.x * v.x; q1 += v.y * v.y; q2 += v.z * v.z; q3 += v.w * v.w;
    }
    sh[0][g][cq * 4 + 0] = s0; sh[0][g][cq * 4 + 1] = s1;
    sh[0][g][cq * 4 + 2] = s2; sh[0][g][cq * 4 + 3] = s3;
    sh[1][g][cq * 4 + 0] = q0; sh[1][g][cq * 4 + 1] = q1;
    sh[1][g][cq * 4 + 2] = q2; sh[1][g][cq * 4 + 3] = q3;
    __syncthreads();
    if (t < 64) {
        float S = 0.f, Q = 0.f;
#pragma unroll
        for (int j = 0; j < 16; j++) { S += sh[0][j][t]; Q += sh[1][j][t]; }
        atomicAdd(&d_bn[t], (double)S);
        atomicAdd(&d_bn[64 + t], (double)Q);
    }
}
__global__ void bn_final(const float* __restrict__ gg, const float* __restrict__ bb) {
    int c = threadIdx.x;
    double mean = d_bn[c] / (double)N_NODES;
    double var = d_bn[64 + c] / (double)N_NODES - mean * mean;
    double sc = (double)gg[c] / sqrt(var + 1e-5);
    d_scale[c] = (float)sc;
    d_shift[c] = (float)((double)bb[c] - mean * sc);
    d_bn[c] = 0.0;
    d_bn[64 + c] = 0.0;
}

// ---------------- A/B precompute via tensor cores (single tile/block) ----------------
__global__ void __launch_bounds__(256) ab_kernel(const float* __restrict__ w1,
                                                 const float* __restrict__ b1) {
    __shared__ uint2 s_wf[2048];
    __shared__ float s_b1[64];
    int t = threadIdx.x, w = t >> 5, l = t & 31;
    int r = l >> 2, c4 = l & 3;

    for (int idx = t; idx < 2048; idx += 256) {
        int lane = idx & 31, fi = idx >> 5;
        int nt = fi >> 2, kt = fi & 3;
        int n = nt * 8 + (lane >> 2), c = lane & 3;
        int k0 = kt * 16 + 2 * c;
        float v00, v01, v10, v11;
        if (n < 64) {
            v00 = w1[k0 * 64 + n]       - w1[(k0 + 64) * 64 + n];
            v01 = w1[(k0 + 1) * 64 + n] - w1[(k0 + 65) * 64 + n];
            v10 = w1[(k0 + 8) * 64 + n] - w1[(k0 + 72) * 64 + n];
            v11 = w1[(k0 + 9) * 64 + n] - w1[(k0 + 73) * 64 + n];
        } else {
            int m = n - 64;
            v00 = w1[(k0 + 64) * 64 + m];
            v01 = w1[(k0 + 65) * 64 + m];
            v10 = w1[(k0 + 72) * 64 + m];
            v11 = w1[(k0 + 73) * 64 + m];
        }
        s_wf[idx] = make_uint2(pack_h2(v00, v01), pack_h2(v10, v11));
    }
    if (t < 64) s_b1[t] = b1[t];
    __syncthreads();

    int n0 = (blockIdx.x * 8 + w) * 16;
    if (n0 >= N_NODES) return;

    float sc[4][4], sf[4][4];
#pragma unroll
    for (int kt = 0; kt < 4; kt++) {
        int k0 = kt * 16 + 2 * c4;
        sc[kt][0] = d_scale[k0];     sf[kt][0] = d_shift[k0];
        sc[kt][1] = d_scale[k0 + 1]; sf[kt][1] = d_shift[k0 + 1];
        sc[kt][2] = d_scale[k0 + 8]; sf[kt][2] = d_shift[k0 + 8];
        sc[kt][3] = d_scale[k0 + 9]; sf[kt][3] = d_shift[k0 + 9];
    }

    uint32_t af[4][4];
#pragma unroll
    for (int kt = 0; kt < 4; kt++) {
        int k0 = kt * 16 + 2 * c4;
        float2 h0a = *(const float2*)&d_h[(n0 + r) * 64 + k0];
        float2 h0b = *(const float2*)&d_h[(n0 + r) * 64 + k0 + 8];
        float2 h1a = *(const float2*)&d_h[(n0 + r + 8) * 64 + k0];
        float2 h1b = *(const float2*)&d_h[(n0 + r + 8) * 64 + k0 + 8];
        af[kt][0] = pack_h2(h0a.x * sc[kt][0] + sf[kt][0], h0a.y * sc[kt][1] + sf[kt][1]);
        af[kt][1] = pack_h2(h1a.x * sc[kt][0] + sf[kt][0], h1a.y * sc[kt][1] + sf[kt][1]);
        af[kt][2] = pack_h2(h0b.x * sc[kt][2] + sf[kt][2], h0b.y * sc[kt][3] + sf[kt][3]);
        af[kt][3] = pack_h2(h1b.x * sc[kt][2] + sf[kt][2], h1b.y * sc[kt][3] + sf[kt][3]);
    }

#pragma unroll
    for (int nt = 0; nt < 16; nt++) {
        float d0 = 0.f, d1 = 0.f, d2 = 0.f, d3 = 0.f;
#pragma unroll
        for (int kt = 0; kt < 4; kt++) {
            uint2 f = s_wf[(nt * 4 + kt) * 32 + l];
            mma_f16(d0, d1, d2, d3, af[kt][0], af[kt][1], af[kt][2], af[kt][3], f.x, f.y);
        }
        int out0 = nt * 8 + 2 * c4;
        if (nt < 8) {
            float bb0 = s_b1[out0], bb1 = s_b1[out0 + 1];
            d0 += bb0; d1 += bb1; d2 += bb0; d3 += bb1;
        }
        int off = c4 * 16 + ((nt & 7) >> 1) * 4 + (nt & 1) * 2;
        __half2 lo = __floats2half2_rn(d0, d1);
        __half2 hi = __floats2half2_rn(d2, d3);
        if (nt < 8) {
            *(__half2*)&d_Ah[(n0 + r) * 64 + off]     = lo;
            *(__half2*)&d_Ah[(n0 + r + 8) * 64 + off] = hi;
        } else {
            *(__half2*)&d_Bh[(n0 + r) * 64 + off]     = lo;
            *(__half2*)&d_Bh[(n0 + r + 8) * 64 + off] = hi;
        }
    }
}

// ---------------- counting sort (16-padded groups) ----------------
__global__ void hist_kernel(const void* __restrict__ ei) {
    int e = blockIdx.x * 256 + threadIdx.x;
    int dd = load_idx(ei, (long long)N_EDGES + e, d_ei32);
    atomicAdd(&d_cnt[dd], 1);
}
__global__ void __launch_bounds__(256) scan_part() {
    __shared__ int sE[256], sG[256];
    int t = threadIdx.x;
    int node = blockIdx.x * 256 + t;
    int c = (node < N_NODES) ? d_cnt[node] : 0;
    int ngn = (c + 15) >> 4;
    sE[t] = ngn * 16; sG[t] = ngn;
    __syncthreads();
    for (int off = 128; off > 0; off >>= 1) {
        if (t < off) { sE[t] += sE[t + off]; sG[t] += sG[t + off]; }
        __syncthreads();
    }
    if (t == 0) { d_bsumE[blockIdx.x] = sE[0]; d_bsumG[blockIdx.x] = sG[0]; }
}
__global__ void __launch_bounds__(256) scan_mid() {
    __shared__ int sE[256], sG[256];
    int t = threadIdx.x;
    sE[t] = (t < SCAN_BLKS) ? d_bsumE[t] : 0;
    sG[t] = (t < SCAN_BLKS) ? d_bsumG[t] : 0;
    __syncthreads();
    for (int off = 1; off < 256; off <<= 1) {
        int vE = (t >= off) ? sE[t - off] : 0;
        int vG = (t >= off) ? sG[t - off] : 0;
        __syncthreads();
        sE[t] += vE; sG[t] += vG;
        __syncthreads();
    }
    if (t < SCAN_BLKS) {
        d_boffE[t] = sE[t] - d_bsumE[t];
        d_boffG[t] = sG[t] - d_bsumG[t];
    }
    if (t == SCAN_BLKS - 1) d_ngroups = sG[t];
}
__global__ void __launch_bounds__(256) scan_emit() {
    __shared__ int sE[256], sG[256];
    int t = threadIdx.x;
    int node = blockIdx.x * 256 + t;
    int c = (node < N_NODES) ? d_cnt[node] : 0;
    int ngn = (c + 15) >> 4;
    sE[t] = ngn * 16; sG[t] = ngn;
    __syncthreads();
    for (int off = 1; off < 256; off <<= 1) {
        int vE = (t >= off) ? sE[t - off] : 0;
        int vG = (t >= off) ? sG[t - off] : 0;
        __syncthreads();
        sE[t] += vE; sG[t] += vG;
        __syncthreads();
    }
    if (node < N_NODES) {
        int ebase = d_boffE[blockIdx.x] + sE[t] - ngn * 16;
        int gbase = d_boffG[blockIdx.x] + sG[t] - ngn;
        d_cur[node] = ebase;
        for (int j = 0; j < ngn; j++) {
            d_gdst[gbase + j] = node;
            int rem = c - 16 * j;
            d_gcnt[gbase + j] = rem < 16 ? rem : 16;
        }
        d_cnt[node] = 0;
    }
}
__global__ void scatter_kernel(const void* __restrict__ ei) {
    int e = blockIdx.x * 256 + threadIdx.x;
    int is32 = d_ei32;
    int ss = load_idx(ei, e, is32);
    int dd = load_idx(ei, (long long)N_EDGES + e, is32);
    int p = atomicAdd(&d_cur[dd], 1);
    d_srcP[p] = ss;
}

__global__ void agg_init() { d_agg[blockIdx.x * 256 + threadIdx.x] = ENC_NINF; }

// ---------------- edge kernel: grid-stride (434.7us config) ----------------
__global__ void __launch_bounds__(256, 3) edge_kernel(const float* __restrict__ w2) {
    __shared__ uint4 s_wf[16 * 32];
    int t = threadIdx.x, w = t >> 5, l = t & 31;

    for (int idx = t; idx < 512; idx += 256) {
        int lane = idx & 31, fi = idx >> 5;
        int chb = fi >> 2, kt = fi & 3;
        int rr = lane >> 2, cc = lane & 3;
        int ch0 = chb * 16 + rr, ch1 = ch0 + 8;
        int k0 = kt * 16 + 2 * cc;
        uint32_t a0 = pack_h2(w2[k0 * 64 + ch0],       w2[(k0 + 1) * 64 + ch0]);
        uint32_t a1 = pack_h2(w2[k0 * 64 + ch1],       w2[(k0 + 1) * 64 + ch1]);
        uint32_t a2 = pack_h2(w2[(k0 + 8) * 64 + ch0], w2[(k0 + 9) * 64 + ch0]);
        uint32_t a3 = pack_h2(w2[(k0 + 8) * 64 + ch1], w2[(k0 + 9) * 64 + ch1]);
        s_wf[idx] = make_uint4(a0, a1, a2, a3);
    }
    __syncthreads();

    int ng = d_ngroups;
    int r = l >> 2, c4 = l & 3;
    const uint4* pA = (const uint4*)d_Ah;
    const uint4* pB = (const uint4*)d_Bh;
    const float NINF = -__int_as_float(0x7F800000) * 1.f;

    for (int g = blockIdx.x * 8 + w; g < ng; g += NWARPS) {
        int gd = d_gdst[g];
        int gc = d_gcnt[g];
        uint4 Au0 = pA[gd * 8 + c4 * 2];
        uint4 Au1 = pA[gd * 8 + c4 * 2 + 1];

        float vmax[4][2];
#pragma unroll
        for (int i = 0; i < 4; i++) { vmax[i][0] = NINF; vmax[i][1] = NINF; }

#pragma unroll
        for (int eb = 0; eb < 2; eb++) {
            int ns = d_srcP[g * 16 + eb * 8 + r];
            uint4 Bu0 = pB[ns * 8 + c4 * 2];
            uint4 Bu1 = pB[ns * 8 + c4 * 2 + 1];
            uint32_t p00 = haz(Au0.x, Bu0.x), p01 = haz(Au0.y, Bu0.y);
            uint32_t p10 = haz(Au0.z, Bu0.z), p11 = haz(Au0.w, Bu0.w);
            uint32_t p20 = haz(Au1.x, Bu1.x), p21 = haz(Au1.y, Bu1.y);
            uint32_t p30 = haz(Au1.z, Bu1.z), p31 = haz(Au1.w, Bu1.w);
            int e0 = eb * 8 + 2 * c4;
            bool m0 = e0 < gc, m1 = e0 + 1 < gc;
#pragma unroll
            for (int chb = 0; chb < 4; chb++) {
                float d0 = 0.f, d1 = 0.f, d2 = 0.f, d3 = 0.f;
                uint4 f;
                f = s_wf[(chb * 4 + 0) * 32 + l];
                mma_f16(d0, d1, d2, d3, f.x, f.y, f.z, f.w, p00, p01);
                f = s_wf[(chb * 4 + 1) * 32 + l];
                mma_f16(d0, d1, d2, d3, f.x, f.y, f.z, f.w, p10, p11);
                f = s_wf[(chb * 4 + 2) * 32 + l];
                mma_f16(d0, d1, d2, d3, f.x, f.y, f.z, f.w, p20, p21);
                f = s_wf[(chb * 4 + 3) * 32 + l];
                mma_f16(d0, d1, d2, d3, f.x, f.y, f.z, f.w, p30, p31);
                vmax[chb][0] = fmaxf(vmax[chb][0], m0 ? d0 : NINF);
                vmax[chb][0] = fmaxf(vmax[chb][0], m1 ? d1 : NINF);
                vmax[chb][1] = fmaxf(vmax[chb][1], m0 ? d2 : NINF);
                vmax[chb][1] = fmaxf(vmax[chb][1], m1 ? d3 : NINF);
            }
        }

#pragma unroll
        for (int chb = 0; chb < 4; chb++) {
#pragma unroll
            for (int j = 0; j < 2; j++) {
                float v = vmax[chb][j];
                v = fmaxf(v, __shfl_xor_sync(0xFFFFFFFFu, v, 1));
                v = fmaxf(v, __shfl_xor_sync(0xFFFFFFFFu, v, 2));
                vmax[chb][j] = v;
            }
        }
        if (c4 == 0) {
#pragma unroll
            for (int chb = 0; chb < 4; chb++) {
#pragma unroll
                for (int j = 0; j < 2; j++) {
                    int ch = chb * 16 + j * 8 + r;
                    atomicMax(&d_agg[gd * 64 + ch], encf(vmax[chb][j]));
                }
            }
        }
    }
}

// ---------------- decode fused with bn partials (skip d_h store on last block) ----------------
__global__ void __launch_bounds__(256) decode_bn_kernel(int blk,
                                                        const float* __restrict__ b2,
                                                        int do_bn) {
    __shared__ float sh[2][16][64];
    int t = threadIdx.x;
    int cq = t & 15, g = t >> 4;
    float4 bb = *(const float4*)&b2[cq * 4];
    float s0 = 0.f, s1 = 0.f, s2 = 0.f, s3 = 0.f;
    float q0 = 0.f, q1 = 0.f, q2 = 0.f, q3 = 0.f;
    for (int n = blockIdx.x * 16 + g; n < N_NODES; n += DEC_GRID * 16) {
        uint4 e = *(uint4*)&d_agg[n * 64 + cq * 4];
        *(uint4*)&d_agg[n * 64 + cq * 4] = make_uint4(ENC_NINF, ENC_NINF, ENC_NINF, ENC_NINF);
        float v0 = (e.x == ENC_NINF) ? 0.f : fmaxf(decf(e.x) + bb.x, 0.f);
        float v1 = (e.y == ENC_NINF) ? 0.f : fmaxf(decf(e.y) + bb.y, 0.f);
        float v2 = (e.z == ENC_NINF) ? 0.f : fmaxf(decf(e.z) + bb.z, 0.f);
        float v3 = (e.w == ENC_NINF) ? 0.f : fmaxf(decf(e.w) + bb.w, 0.f);
        float4 vv = make_float4(v0, v1, v2, v3);
        if (do_bn) *(float4*)&d_h[n * 64 + cq * 4] = vv;   // d_h unused after final block
        *(float4*)&d_cat[n * CATC + blk * 64 + cq * 4] = vv;
        s0 += v0; s1 += v1; s2 += v2; s3 += v3;
        q0 += v0 * v0; q1 += v1 * v1; q2 += v2 * v2; q3 += v3 * v3;
    }
    if (!do_bn) return;
    sh[0][g][cq * 4 + 0] = s0; sh[0][g][cq * 4 + 1] = s1;
    sh[0][g][cq * 4 + 2] = s2; sh[0][g][cq * 4 + 3] = s3;
    sh[1][g][cq * 4 + 0] = q0; sh[1][g][cq * 4 + 1] = q1;
    sh[1][g][cq * 4 + 2] = q2; sh[1][g][cq * 4 + 3] = q3;
    __syncthreads();
    if (t < 64) {
        float S = 0.f, Q = 0.f;
#pragma unroll
        for (int j = 0; j < 16; j++) { S += sh[0][j][t]; Q += sh[1][j][t]; }
        atomicAdd(&d_bn[t], (double)S);
        atomicAdd(&d_bn[64 + t], (double)Q);
    }
}

// ---------------- fused pool + head (per-graph block) ----------------
__global__ void __launch_bounds__(CATC) pool_head_kernel(const void* __restrict__ batch,
                                                         const float* __restrict__ w1,
                                                         const float* __restrict__ b1,
                                                         const float* __restrict__ w2,
                                                         const float* __restrict__ b2,
                                                         float* __restrict__ out) {
    __shared__ int s_se[2];
    __shared__ float sp[CATC];
    __shared__ float shid[MLP_DIM];
    __shared__ float sl[N_CLASSES];
    __shared__ float s_ls;
    int g = blockIdx.x, t = threadIdx.x;

    if (t < 2) {
        int is32 = d_b32;
        int target = g + t;
        int lo = 0, hi = N_NODES;
        while (lo < hi) {
            int mid = (lo + hi) >> 1;
            if (load_idx(batch, mid, is32) < target) lo = mid + 1; else hi = mid;
        }
        s_se[t] = lo;
    }
    __syncthreads();

    int s = s_se[0], e = s_se[1];
    float acc = 0.f;
    for (int n = s; n < e; n++) acc += d_cat[n * CATC + t];
    int cnt = e - s; if (cnt < 1) cnt = 1;
    sp[t] = acc / (float)cnt;
    __syncthreads();

    if (t < MLP_DIM) {
        float a = b1[t];
#pragma unroll 8
        for (int k = 0; k < CATC; k++) a += sp[k] * w1[k * MLP_DIM + t];
        shid[t] = fmaxf(a, 0.f);
    }
    __syncthreads();
    if (t < N_CLASSES) {
        float a = b2[t];
#pragma unroll 8
        for (int k = 0; k < MLP_DIM; k++) a += shid[k] * w2[k * N_CLASSES + t];
        sl[t] = a;
    }
    __syncthreads();
    if (t == 0) {
        float mx = sl[0];
        for (int i = 1; i < N_CLASSES; i++) mx = fmaxf(mx, sl[i]);
        float se = 0.f;
        for (int i = 0; i < N_CLASSES; i++) se += expf(sl[i] - mx);
        s_ls = mx + logf(se);
    }
    __syncthreads();
    if (t < N_CLASSES) out[g * N_CLASSES + t] = sl[t] - s_ls;
}

// ---------------- launch ----------------
extern "C" void kernel_launch(void* const* d_in, const int* in_sizes, int n_in,
                              void* d_out, int out_size) {
    const float* x     = (const float*)d_in[0];
    const void*  ei    = d_in[1];
    const void*  batch = d_in[2];
    const float* fc0_w = (const float*)d_in[3];
    const float* fc0_b = (const float*)d_in[4];
    const float* fc1_w = (const float*)d_in[5];
    const float* fc1_b = (const float*)d_in[6];
    const float* fc2_w = (const float*)d_in[7];
    const float* fc2_b = (const float*)d_in[8];
    const float* bnp[3][6];
    for (int i = 0; i < 3; i++)
        for (int j = 0; j < 6; j++)
            bnp[i][j] = (const float*)d_in[9 + 6 * i + j];
    float* out = (float*)d_out;

    fc0_kernel<<<AB_GRID, 256>>>(x, fc0_w, fc0_b);                   // 1
    bn_stats<<<BN_GRID, 256>>>();                                    // 2
    bn_final<<<1, 64>>>(bnp[0][0], bnp[0][1]);                       // 3
    ab_kernel<<<AB_GRID, 256>>>(bnp[0][2], bnp[0][3]);               // 4 (profiled)
    detect_kernel<<<16, 256>>>((const int*)ei, (const int*)batch);   // 5
    hist_kernel<<<N_EDGES / 256, 256>>>(ei);                         // 6
    scan_part<<<SCAN_BLKS, 256>>>();                                 // 7
    scan_mid<<<1, 256>>>();                                          // 8
    scan_emit<<<SCAN_BLKS, 256>>>();                                 // 9
    scatter_kernel<<<N_EDGES / 256, 256>>>(ei);                      // 10
    agg_init<<<(N_NODES * C) / 256, 256>>>();                        // 11

    for (int i = 0; i < 3; i++) {
        if (i > 0) {
            bn_final<<<1, 64>>>(bnp[i][0], bnp[i][1]);
            ab_kernel<<<AB_GRID, 256>>>(bnp[i][2], bnp[i][3]);
        }
        edge_kernel<<<EDGE_GRID, 256>>>(bnp[i][4]);
        decode_bn_kernel<<<DEC_GRID, 256>>>(i, bnp[i][5], i < 2 ? 1 : 0);
    }

    pool_head_kernel<<<NG, CATC>>>(batch, fc1_w, fc1_b, fc2_w, fc2_b, out);
}